// round 3
// baseline (speedup 1.0000x reference)
#include <cuda_runtime.h>
#include <math.h>

#define BB 256
#define LL 256
#define VV 14
#define EMBD 512
#define HH 128
#define OC 256
#define NP 196
#define NPP 256          // padded pair stride
#define KLIN 32768       // OC*HH
#define NJ 128
#define SPLITK 64
#define KC (KLIN/SPLITK) // 512

typedef unsigned long long ull;

// ---------------- scratch ---------------------------------------------------
__device__ float g_poolT_e[EMBD*NPP];
__device__ float g_poolT_f[EMBD*NPP];
__device__ float g_pbpart[4*2*3*OC*NPP];   // [cs][br][kh][o][p]
__device__ float g_P2[2*3*OC*NPP];         // [br][kh][o][p]
__device__ float g_conv[BB*KLIN];
__device__ float g_partial[SPLITK*BB*NJ];
__device__ float g_vec[BB*NJ];
__device__ float g_r[3*BB*64];
__device__ float g_Lmid[64*256];
__device__ int   g_tok[BB*256];

// ---------------- f32x2 helpers --------------------------------------------
__device__ __forceinline__ ull pk2(float lo, float hi){
    ull r; asm("mov.b64 %0, {%1, %2};" : "=l"(r) : "f"(lo), "f"(hi)); return r;
}
__device__ __forceinline__ void upk2(ull v, float& lo, float& hi){
    asm("mov.b64 {%0, %1}, %2;" : "=f"(lo), "=f"(hi) : "l"(v));
}
__device__ __forceinline__ void ffma2(ull& c, ull a, ull b){
    asm("fma.rn.f32x2 %0, %1, %2, %0;" : "+l"(c) : "l"(a), "l"(b));
}

// ---------------- pooled-pair LUT, both branches ----------------------------
__global__ void k_poolT2(const float* __restrict__ eemb, const float* __restrict__ femb){
    int idx = blockIdx.x*256 + threadIdx.x;        // < 2*EMBD*NPP
    int br = idx / (EMBD*NPP);
    int r  = idx % (EMBD*NPP);
    int c = r >> 8, p = r & 255;
    const float* emb = br ? femb : eemb;
    float v = 0.f;
    if (p < NP){
        int t1 = p / VV, t2 = p % VV;
        v = fmaxf(emb[t1*EMBD + c], emb[t2*EMBD + c]);
    }
    (br ? g_poolT_f : g_poolT_e)[c*NPP + p] = v;
}

// ---------------- pbuild: P2 partials, c-split x4, both branches ------------
__global__ __launch_bounds__(512) void k_pbuild2(const float* __restrict__ ecw,
                                                 const float* __restrict__ fcw){
    int ot = blockIdx.x;          // 0..31 -> 8 o's
    int cs = blockIdx.y;          // 0..3  -> 128 c's
    int br = blockIdx.z;          // 0..1
    const float* cw    = br ? fcw : ecw;
    const float* poolT = br ? g_poolT_f : g_poolT_e;
    int o0 = ot*8, c0 = cs*128;
    __shared__ float ws[8*3*128];                 // [oi][kh][c]
    int tid = threadIdx.x;
    for (int e = tid; e < 3072; e += 512){
        int oi = e / 384, r = e % 384, kh = r >> 7, c = r & 127;
        ws[e] = cw[((size_t)(o0+oi)*EMBD + (c0+c))*9 + 1 + kh*3];
    }
    __syncthreads();
    int pg = tid & 63, oi = tid >> 6;
    int p0 = pg*4;
    ull acc0=0, acc1=0, acc2=0, acc3=0, acc4=0, acc5=0;   // [kh][pair]
    const float* pt  = poolT + (size_t)c0*NPP + p0;
    const float* wsp = ws + oi*384;
    #pragma unroll 4
    for (int c = 0; c < 128; c++){
        float4 pv = *(const float4*)(pt + (size_t)c*NPP);
        ull pa0 = pk2(pv.x, pv.y), pa1 = pk2(pv.z, pv.w);
        float w0 = wsp[c], w1 = wsp[128+c], w2 = wsp[256+c];
        ull b0 = pk2(w0,w0), b1 = pk2(w1,w1), b2 = pk2(w2,w2);
        ffma2(acc0, pa0, b0); ffma2(acc1, pa1, b0);
        ffma2(acc2, pa0, b1); ffma2(acc3, pa1, b1);
        ffma2(acc4, pa0, b2); ffma2(acc5, pa1, b2);
    }
    size_t base = (((size_t)(cs*2 + br)*3)*OC + (o0+oi))*NPP + p0;
    *(ulonglong2*)(g_pbpart + base)            = make_ulonglong2(acc0, acc1);
    *(ulonglong2*)(g_pbpart + base + OC*NPP)   = make_ulonglong2(acc2, acc3);
    *(ulonglong2*)(g_pbpart + base + 2*OC*NPP) = make_ulonglong2(acc4, acc5);
}

__global__ void k_pbreduce(){
    int idx = blockIdx.x*256 + threadIdx.x;        // < 2*3*OC*NPP (=393216)
    int br = idx / (3*OC*NPP);
    int inner = idx % (3*OC*NPP);
    float s = g_pbpart[(0*2+br)*(3*OC*NPP) + inner]
            + g_pbpart[(1*2+br)*(3*OC*NPP) + inner]
            + g_pbpart[(2*2+br)*(3*OC*NPP) + inner]
            + g_pbpart[(3*2+br)*(3*OC*NPP) + inner];
    g_P2[idx] = s;
}

// ---------------- conv via smem-staged LUT gather ---------------------------
__global__ __launch_bounds__(256) void k_conv2(int which, const int* __restrict__ x,
                                               const float* __restrict__ bias){
    int ot = blockIdx.x;   // 0..31 -> 8 o's
    int bt = blockIdx.y;   // 0..15 -> 16 b's
    __shared__ float sP2[3*8*256];    // [kh][oi][p] 24KB
    __shared__ int   spi[16*128];     // 8KB
    __shared__ float sbias[8];
    const float* P2 = g_P2 + (size_t)which*(3*OC*NPP);
    int o0 = ot*8, b0 = bt*16, tid = threadIdx.x;
    for (int e = tid; e < 6144; e += 256){
        int kh = e / 2048, r = e & 2047, oi = r >> 8, p = r & 255;
        sP2[e] = P2[(size_t)kh*OC*NPP + (o0+oi)*NPP + p];
    }
    const int* tok = which ? g_tok : x;
    for (int e = tid; e < 2048; e += 256){
        int bi = e >> 7, h = e & 127;
        const int* tb = tok + (size_t)(b0+bi)*LL;
        spi[e] = tb[2*h]*VV + tb[2*h+1];
    }
    if (tid < 8) sbias[tid] = bias[o0 + tid];
    __syncthreads();
    #pragma unroll 2
    for (int r = 0; r < 64; r++){
        int idx = r*256 + tid;           // 16384 outputs
        int h = idx & 127, oi = (idx >> 7) & 7, bi = idx >> 10;
        const int* pib = spi + bi*128;
        const float* so = sP2 + oi*256;
        float v = sbias[oi];
        if (h > 0)   v += so[pib[h-1]];
        v += so[2048 + pib[h]];
        if (h < 127) v += so[4096 + pib[h+1]];
        g_conv[(size_t)(b0+bi)*KLIN + (o0+oi)*128 + h] = v;
    }
}

// ---------------- split-K GEMM, f32x2, double-buffered ----------------------
__global__ __launch_bounds__(256) void k_gemm2(const float* __restrict__ W){
    __shared__ float As[2][16][128];   // 2 x 8KB
    __shared__ ull   Bs[2][16][128];   // 2 x 16KB (pre-dup (w,w))
    const float* A = g_conv;
    int tid = threadIdx.x;
    int m0 = blockIdx.x * 128;
    int k0 = blockIdx.y * KC;
    int lk = tid & 15, lm = tid >> 4;
    int bj = tid & 127, bk = tid >> 7;
    int tx = tid & 15, ty = tid >> 4;
    ull acc[4][8];
    #pragma unroll
    for (int i=0;i<4;i++)
        #pragma unroll
        for (int j=0;j<8;j++) acc[i][j] = 0ull;

    float ra[8], rb[8];
    // prologue: tile 0
    #pragma unroll
    for (int i=0;i<8;i++) ra[i] = A[(size_t)(m0 + lm + i*16)*KLIN + k0 + lk];
    #pragma unroll
    for (int i=0;i<8;i++) rb[i] = W[(size_t)(k0 + bk + i*2)*NJ + bj];
    #pragma unroll
    for (int i=0;i<8;i++) As[0][lk][lm + i*16] = ra[i];
    #pragma unroll
    for (int i=0;i<8;i++) Bs[0][bk + i*2][bj] = pk2(rb[i], rb[i]);
    __syncthreads();

    int buf = 0;
    for (int t = 16; t < KC; t += 16){
        #pragma unroll
        for (int i=0;i<8;i++) ra[i] = A[(size_t)(m0 + lm + i*16)*KLIN + k0 + t + lk];
        #pragma unroll
        for (int i=0;i<8;i++) rb[i] = W[(size_t)(k0 + t + bk + i*2)*NJ + bj];
        #pragma unroll
        for (int kk=0; kk<16; kk++){
            ulonglong2 a01 = *(const ulonglong2*)&As[buf][kk][ty*8];
            ulonglong2 a23 = *(const ulonglong2*)&As[buf][kk][ty*8 + 4];
            ulonglong2 q0 = *(const ulonglong2*)&Bs[buf][kk][tx*4];
            ulonglong2 q1 = *(const ulonglong2*)&Bs[buf][kk][tx*4 + 2];
            ulonglong2 q2 = *(const ulonglong2*)&Bs[buf][kk][64 + tx*4];
            ulonglong2 q3 = *(const ulonglong2*)&Bs[buf][kk][64 + tx*4 + 2];
            ull ap[4] = {a01.x, a01.y, a23.x, a23.y};
            ull bd[8] = {q0.x, q0.y, q1.x, q1.y, q2.x, q2.y, q3.x, q3.y};
            #pragma unroll
            for (int i=0;i<4;i++)
                #pragma unroll
                for (int j=0;j<8;j++)
                    ffma2(acc[i][j], ap[i], bd[j]);
        }
        #pragma unroll
        for (int i=0;i<8;i++) As[buf^1][lk][lm + i*16] = ra[i];
        #pragma unroll
        for (int i=0;i<8;i++) Bs[buf^1][bk + i*2][bj] = pk2(rb[i], rb[i]);
        __syncthreads();
        buf ^= 1;
    }
    // final tile
    #pragma unroll
    for (int kk=0; kk<16; kk++){
        ulonglong2 a01 = *(const ulonglong2*)&As[buf][kk][ty*8];
        ulonglong2 a23 = *(const ulonglong2*)&As[buf][kk][ty*8 + 4];
        ulonglong2 q0 = *(const ulonglong2*)&Bs[buf][kk][tx*4];
        ulonglong2 q1 = *(const ulonglong2*)&Bs[buf][kk][tx*4 + 2];
        ulonglong2 q2 = *(const ulonglong2*)&Bs[buf][kk][64 + tx*4];
        ulonglong2 q3 = *(const ulonglong2*)&Bs[buf][kk][64 + tx*4 + 2];
        ull ap[4] = {a01.x, a01.y, a23.x, a23.y};
        ull bd[8] = {q0.x, q0.y, q1.x, q1.y, q2.x, q2.y, q3.x, q3.y};
        #pragma unroll
        for (int i=0;i<4;i++)
            #pragma unroll
            for (int j=0;j<8;j++)
                ffma2(acc[i][j], ap[i], bd[j]);
    }

    float* outp = g_partial + (size_t)blockIdx.y * (BB*NJ);
    #pragma unroll
    for (int i=0;i<4;i++){
        int mlo = m0 + ty*8 + 2*i;
        float rlo[8], rhi[8];
        #pragma unroll
        for (int j=0;j<8;j++) upk2(acc[i][j], rlo[j], rhi[j]);
        *(float4*)&outp[(size_t)mlo*NJ + tx*4]          = make_float4(rlo[0],rlo[1],rlo[2],rlo[3]);
        *(float4*)&outp[(size_t)mlo*NJ + 64 + tx*4]     = make_float4(rlo[4],rlo[5],rlo[6],rlo[7]);
        *(float4*)&outp[(size_t)(mlo+1)*NJ + tx*4]      = make_float4(rhi[0],rhi[1],rhi[2],rhi[3]);
        *(float4*)&outp[(size_t)(mlo+1)*NJ + 64 + tx*4] = make_float4(rhi[4],rhi[5],rhi[6],rhi[7]);
    }
}

// ---------------- split-K reduce + softmax (enemy) --------------------------
__global__ void k_redsm(const float* __restrict__ bias){
    __shared__ float red[128];
    int b = blockIdx.x, t = threadIdx.x;
    float s = bias[t];
    #pragma unroll 8
    for (int kz=0; kz<SPLITK; kz++) s += g_partial[(size_t)(kz*BB + b)*NJ + t];
    float v = s;
    red[t] = v; __syncthreads();
    for (int st=64; st; st>>=1){ if (t < st) red[t] = fmaxf(red[t], red[t+st]); __syncthreads(); }
    float mx = red[0]; __syncthreads();
    float e = expf(v - mx);
    red[t] = e; __syncthreads();
    for (int st=64; st; st>>=1){ if (t < st) red[t] += red[t+st]; __syncthreads(); }
    g_vec[b*128 + t] = e / red[0];
}

// ---------------- manipulator conv (collapsed), fused weight-sum ------------
__global__ void k_rgemm2(const float* __restrict__ mcw, const float* __restrict__ mcb){
    int idx = blockIdx.x*256 + threadIdx.x;     // < 3*BB*64
    if (idx >= 3*BB*64) return;
    int v = idx / (BB*64);
    int rem = idx % (BB*64);
    int b = rem / 64, o = rem % 64;
    const float* eo = g_vec + b*128;
    float s = mcb[o];
    for (int c=0; c<128; c++){
        int base = (o*128 + c)*9;
        float w0 = mcw[base+1], w1 = mcw[base+4], w2 = mcw[base+7];
        float ws = (v==0) ? (w1+w2) : (v==1) ? ((w0+w1)+w2) : (w0+w1);
        s = fmaf(eo[c], ws, s);
    }
    g_r[idx] = fmaxf(s, 0.f);
}

__global__ void k_lmid(const float* __restrict__ mlw){
    int idx = blockIdx.x*256 + threadIdx.x;     // < 64*256
    if (idx >= 64*256) return;
    int o = idx >> 8, j = idx & 255;
    float s = 0.f;
    for (int h=1; h<127; h++) s += mlw[(size_t)(o*128 + h)*256 + j];
    g_Lmid[idx] = s;
}

__global__ void k_mtok(const float* __restrict__ mlw, const float* __restrict__ mlb){
    int idx = blockIdx.x*256 + threadIdx.x;     // < BB*256
    if (idx >= BB*256) return;
    int b = idx >> 8, j = idx & 255;
    const float* r0   = g_r + 0*BB*64 + b*64;
    const float* ri   = g_r + 1*BB*64 + b*64;
    const float* r127 = g_r + 2*BB*64 + b*64;
    float s = mlb[j];
    for (int o=0; o<64; o++){
        s = fmaf(r0[o],   mlw[(size_t)o*32768 + j],          s);
        s = fmaf(ri[o],   g_Lmid[o*256 + j],                 s);
        s = fmaf(r127[o], mlw[(size_t)o*32768 + 32512 + j],  s);
    }
    int t = (int)floorf(fabsf(s) * 100.0f);
    g_tok[idx] = t % VV;
}

// ---------------- friend: reduce + final linear + softmax -------------------
__global__ void k_redlin2(const float* __restrict__ bias, const float* __restrict__ w2,
                          const float* __restrict__ b2, float* __restrict__ out){
    __shared__ float f[128];
    int b = blockIdx.x, t = threadIdx.x;
    float s = bias[t];
    #pragma unroll 8
    for (int kz=0; kz<SPLITK; kz++) s += g_partial[(size_t)(kz*BB + b)*NJ + t];
    f[t] = s; __syncthreads();
    if (t < 32){
        float logit = -INFINITY;
        if (t < VV){
            logit = b2[t];
            for (int j=0; j<128; j++) logit = fmaf(f[j], w2[j*VV + t], logit);
        }
        float mx = logit;
        for (int off=16; off; off>>=1) mx = fmaxf(mx, __shfl_xor_sync(0xffffffffu, mx, off));
        float e = (t < VV) ? expf(logit - mx) : 0.f;
        float sm = e;
        for (int off=16; off; off>>=1) sm += __shfl_xor_sync(0xffffffffu, sm, off);
        if (t < VV) out[b*VV + t] = e / sm;
    }
}

// ---------------- launch ----------------------------------------------------
extern "C" void kernel_launch(void* const* d_in, const int* in_sizes, int n_in,
                              void* d_out, int out_size){
    const int*   x    = (const int*)  d_in[0];
    const float* eemb = (const float*)d_in[1];
    const float* ecw  = (const float*)d_in[2];
    const float* ecb  = (const float*)d_in[3];
    const float* elw  = (const float*)d_in[4];
    const float* elb  = (const float*)d_in[5];
    // d_in[6] rand_proj: dead (fog_of_war == identity permutation)
    const float* mcw  = (const float*)d_in[7];
    const float* mcb  = (const float*)d_in[8];
    const float* mlw  = (const float*)d_in[9];
    const float* mlb  = (const float*)d_in[10];
    const float* femb = (const float*)d_in[11];
    const float* fcw  = (const float*)d_in[12];
    const float* fcb  = (const float*)d_in[13];
    const float* flw1 = (const float*)d_in[14];
    const float* flb1 = (const float*)d_in[15];
    const float* flw2 = (const float*)d_in[16];
    const float* flb2 = (const float*)d_in[17];
    float* out = (float*)d_out;

    // LUT builds for both branches
    k_poolT2<<<(2*EMBD*NPP)/256, 256>>>(eemb, femb);
    k_pbuild2<<<dim3(32,4,2), 512>>>(ecw, fcw);
    k_pbreduce<<<(2*3*OC*NPP)/256, 256>>>();

    // enemy branch
    k_conv2<<<dim3(32,16), 256>>>(0, x, ecb);
    k_gemm2<<<dim3(2, SPLITK), 256>>>(elw);
    k_redsm<<<BB, 128>>>(elb);

    // manipulator -> tokens
    k_rgemm2<<<(3*BB*64)/256, 256>>>(mcw, mcb);
    k_lmid<<<(64*256)/256, 256>>>(mlw);
    k_mtok<<<(BB*256)/256, 256>>>(mlw, mlb);

    // friend branch
    k_conv2<<<dim3(32,16), 256>>>(1, x, fcb);
    k_gemm2<<<dim3(2, SPLITK), 256>>>(flw1);
    k_redlin2<<<BB, 128>>>(flb1, flw2, flb2, out);
}

// round 4
// speedup vs baseline: 1.4818x; 1.4818x over previous
#include <cuda_runtime.h>
#include <math.h>

#define BB 256
#define LL 256
#define VV 14
#define EMBD 512
#define HH 128
#define OC 256
#define NP 196
#define NPP 256          // padded pair stride
#define KLIN 32768       // OC*HH
#define NJ 128
#define SPLITK 128
#define KC (KLIN/SPLITK) // 256

typedef unsigned long long ull;

// ---------------- scratch ---------------------------------------------------
__device__ float g_poolT_e[EMBD*NPP];
__device__ float g_poolT_f[EMBD*NPP];
__device__ float g_pbpart[4*2*3*OC*NPP];   // [cs][br][kh][o][p]
__device__ float g_P2[2*3*OC*NPP];         // [br][kh][o][p]
__device__ float g_conv[BB*KLIN];
__device__ float g_partial[SPLITK*BB*NJ];  // 16.8MB
__device__ float g_vec[BB*NJ];
__device__ float g_r[3*BB*64];
__device__ float g_Wsum[3*64*128];
__device__ float g_Lmid[64*256];
__device__ int   g_tok[BB*256];

// ---------------- f32x2 helpers --------------------------------------------
__device__ __forceinline__ ull pk2(float lo, float hi){
    ull r; asm("mov.b64 %0, {%1, %2};" : "=l"(r) : "f"(lo), "f"(hi)); return r;
}
__device__ __forceinline__ void upk2(ull v, float& lo, float& hi){
    asm("mov.b64 {%0, %1}, %2;" : "=f"(lo), "=f"(hi) : "l"(v));
}
__device__ __forceinline__ void ffma2(ull& c, ull a, ull b){
    asm("fma.rn.f32x2 %0, %1, %2, %0;" : "+l"(c) : "l"(a), "l"(b));
}

// ---------------- pooled-pair LUT, both branches ----------------------------
__global__ void k_poolT2(const float* __restrict__ eemb, const float* __restrict__ femb){
    int idx = blockIdx.x*256 + threadIdx.x;        // < 2*EMBD*NPP
    int br = idx / (EMBD*NPP);
    int r  = idx % (EMBD*NPP);
    int c = r >> 8, p = r & 255;
    const float* emb = br ? femb : eemb;
    float v = 0.f;
    if (p < NP){
        int t1 = p / VV, t2 = p % VV;
        v = fmaxf(emb[t1*EMBD + c], emb[t2*EMBD + c]);
    }
    (br ? g_poolT_f : g_poolT_e)[c*NPP + p] = v;
}

// ---------------- pbuild: P2 partials, c-split x4, both branches ------------
__global__ __launch_bounds__(512) void k_pbuild2(const float* __restrict__ ecw,
                                                 const float* __restrict__ fcw){
    int ot = blockIdx.x;          // 0..31 -> 8 o's
    int cs = blockIdx.y;          // 0..3  -> 128 c's
    int br = blockIdx.z;          // 0..1
    const float* cw    = br ? fcw : ecw;
    const float* poolT = br ? g_poolT_f : g_poolT_e;
    int o0 = ot*8, c0 = cs*128;
    __shared__ float ws[8*3*128];                 // [oi][kh][c]
    int tid = threadIdx.x;
    for (int e = tid; e < 3072; e += 512){
        int oi = e / 384, r = e % 384, kh = r >> 7, c = r & 127;
        ws[e] = cw[((size_t)(o0+oi)*EMBD + (c0+c))*9 + 1 + kh*3];
    }
    __syncthreads();
    int pg = tid & 63, oi = tid >> 6;
    int p0 = pg*4;
    ull acc0=0, acc1=0, acc2=0, acc3=0, acc4=0, acc5=0;   // [kh][pair]
    const float* pt  = poolT + (size_t)c0*NPP + p0;
    const float* wsp = ws + oi*384;
    #pragma unroll 4
    for (int c = 0; c < 128; c++){
        float4 pv = *(const float4*)(pt + (size_t)c*NPP);
        ull pa0 = pk2(pv.x, pv.y), pa1 = pk2(pv.z, pv.w);
        float w0 = wsp[c], w1 = wsp[128+c], w2 = wsp[256+c];
        ull b0 = pk2(w0,w0), b1 = pk2(w1,w1), b2 = pk2(w2,w2);
        ffma2(acc0, pa0, b0); ffma2(acc1, pa1, b0);
        ffma2(acc2, pa0, b1); ffma2(acc3, pa1, b1);
        ffma2(acc4, pa0, b2); ffma2(acc5, pa1, b2);
    }
    size_t base = (((size_t)(cs*2 + br)*3)*OC + (o0+oi))*NPP + p0;
    *(ulonglong2*)(g_pbpart + base)            = make_ulonglong2(acc0, acc1);
    *(ulonglong2*)(g_pbpart + base + OC*NPP)   = make_ulonglong2(acc2, acc3);
    *(ulonglong2*)(g_pbpart + base + 2*OC*NPP) = make_ulonglong2(acc4, acc5);
}

__global__ void k_pbreduce(){
    int idx = blockIdx.x*256 + threadIdx.x;        // < 2*3*OC*NPP
    int br = idx / (3*OC*NPP);
    int inner = idx % (3*OC*NPP);
    float s = g_pbpart[(0*2+br)*(3*OC*NPP) + inner]
            + g_pbpart[(1*2+br)*(3*OC*NPP) + inner]
            + g_pbpart[(2*2+br)*(3*OC*NPP) + inner]
            + g_pbpart[(3*2+br)*(3*OC*NPP) + inner];
    g_P2[idx] = s;
}

// ---------------- conv via smem-staged LUT gather ---------------------------
__global__ __launch_bounds__(256) void k_conv2(int which, const int* __restrict__ x,
                                               const float* __restrict__ bias){
    int ot = blockIdx.x;   // 0..31 -> 8 o's
    int bt = blockIdx.y;   // 0..15 -> 16 b's
    __shared__ float sP2[3*8*256];    // [kh][oi][p]
    __shared__ int   spi[16*128];
    __shared__ float sbias[8];
    const float* P2 = g_P2 + (size_t)which*(3*OC*NPP);
    int o0 = ot*8, b0 = bt*16, tid = threadIdx.x;
    for (int e = tid; e < 6144; e += 256){
        int kh = e / 2048, r = e & 2047, oi = r >> 8, p = r & 255;
        sP2[e] = P2[(size_t)kh*OC*NPP + (o0+oi)*NPP + p];
    }
    const int* tok = which ? g_tok : x;
    for (int e = tid; e < 2048; e += 256){
        int bi = e >> 7, h = e & 127;
        const int* tb = tok + (size_t)(b0+bi)*LL;
        spi[e] = tb[2*h]*VV + tb[2*h+1];
    }
    if (tid < 8) sbias[tid] = bias[o0 + tid];
    __syncthreads();
    #pragma unroll 2
    for (int r = 0; r < 64; r++){
        int idx = r*256 + tid;
        int h = idx & 127, oi = (idx >> 7) & 7, bi = idx >> 10;
        const int* pib = spi + bi*128;
        const float* so = sP2 + oi*256;
        float v = sbias[oi];
        if (h > 0)   v += so[pib[h-1]];
        v += so[2048 + pib[h]];
        if (h < 127) v += so[4096 + pib[h+1]];
        g_conv[(size_t)(b0+bi)*KLIN + (o0+oi)*128 + h] = v;
    }
}

// ---------------- split-K GEMM: r2 balanced inner + double buffer -----------
// grid (2, SPLITK), block 256. Tile 128(M) x 128(N), K-chunk KC=256.
__global__ __launch_bounds__(256) void k_gemm2(const float* __restrict__ W){
    __shared__ float As[2][16][128];   // 2 x 8KB
    __shared__ float Bs[2][16][128];   // 2 x 8KB
    const float* A = g_conv;
    int tid = threadIdx.x;
    int m0 = blockIdx.x * 128;
    int k0 = blockIdx.y * KC;
    int lk = tid & 15, lm = tid >> 4;
    int bj = tid & 127, bk = tid >> 7;
    int tx = tid & 15, ty = tid >> 4;
    ull acc[4][8];
    #pragma unroll
    for (int i=0;i<4;i++)
        #pragma unroll
        for (int j=0;j<8;j++) acc[i][j] = 0ull;

    float ra[8], rb[8];
    // prologue: tile 0
    #pragma unroll
    for (int i=0;i<8;i++) ra[i] = A[(size_t)(m0 + lm + i*16)*KLIN + k0 + lk];
    #pragma unroll
    for (int i=0;i<8;i++) rb[i] = W[(size_t)(k0 + bk + i*2)*NJ + bj];
    #pragma unroll
    for (int i=0;i<8;i++) As[0][lk][lm + i*16] = ra[i];
    #pragma unroll
    for (int i=0;i<8;i++) Bs[0][bk + i*2][bj] = rb[i];
    __syncthreads();

    int buf = 0;
    for (int t = 16; t < KC; t += 16){
        #pragma unroll
        for (int i=0;i<8;i++) ra[i] = A[(size_t)(m0 + lm + i*16)*KLIN + k0 + t + lk];
        #pragma unroll
        for (int i=0;i<8;i++) rb[i] = W[(size_t)(k0 + t + bk + i*2)*NJ + bj];
        #pragma unroll
        for (int kk=0; kk<16; kk++){
            float4 a0 = *(const float4*)&As[buf][kk][ty*8];
            float4 a1 = *(const float4*)&As[buf][kk][ty*8 + 4];
            float4 b0 = *(const float4*)&Bs[buf][kk][tx*4];
            float4 b1 = *(const float4*)&Bs[buf][kk][64 + tx*4];
            ull ap[4] = { pk2(a0.x,a0.y), pk2(a0.z,a0.w),
                          pk2(a1.x,a1.y), pk2(a1.z,a1.w) };
            ull bd[8] = { pk2(b0.x,b0.x), pk2(b0.y,b0.y),
                          pk2(b0.z,b0.z), pk2(b0.w,b0.w),
                          pk2(b1.x,b1.x), pk2(b1.y,b1.y),
                          pk2(b1.z,b1.z), pk2(b1.w,b1.w) };
            #pragma unroll
            for (int i=0;i<4;i++)
                #pragma unroll
                for (int j=0;j<8;j++)
                    ffma2(acc[i][j], ap[i], bd[j]);
        }
        #pragma unroll
        for (int i=0;i<8;i++) As[buf^1][lk][lm + i*16] = ra[i];
        #pragma unroll
        for (int i=0;i<8;i++) Bs[buf^1][bk + i*2][bj] = rb[i];
        __syncthreads();
        buf ^= 1;
    }
    // final tile
    #pragma unroll
    for (int kk=0; kk<16; kk++){
        float4 a0 = *(const float4*)&As[buf][kk][ty*8];
        float4 a1 = *(const float4*)&As[buf][kk][ty*8 + 4];
        float4 b0 = *(const float4*)&Bs[buf][kk][tx*4];
        float4 b1 = *(const float4*)&Bs[buf][kk][64 + tx*4];
        ull ap[4] = { pk2(a0.x,a0.y), pk2(a0.z,a0.w),
                      pk2(a1.x,a1.y), pk2(a1.z,a1.w) };
        ull bd[8] = { pk2(b0.x,b0.x), pk2(b0.y,b0.y),
                      pk2(b0.z,b0.z), pk2(b0.w,b0.w),
                      pk2(b1.x,b1.x), pk2(b1.y,b1.y),
                      pk2(b1.z,b1.z), pk2(b1.w,b1.w) };
        #pragma unroll
        for (int i=0;i<4;i++)
            #pragma unroll
            for (int j=0;j<8;j++)
                ffma2(acc[i][j], ap[i], bd[j]);
    }

    float* outp = g_partial + (size_t)blockIdx.y * (BB*NJ);
    #pragma unroll
    for (int i=0;i<4;i++){
        int mlo = m0 + ty*8 + 2*i;
        float rlo[8], rhi[8];
        #pragma unroll
        for (int j=0;j<8;j++) upk2(acc[i][j], rlo[j], rhi[j]);
        *(float4*)&outp[(size_t)mlo*NJ + tx*4]          = make_float4(rlo[0],rlo[1],rlo[2],rlo[3]);
        *(float4*)&outp[(size_t)mlo*NJ + 64 + tx*4]     = make_float4(rlo[4],rlo[5],rlo[6],rlo[7]);
        *(float4*)&outp[(size_t)(mlo+1)*NJ + tx*4]      = make_float4(rhi[0],rhi[1],rhi[2],rhi[3]);
        *(float4*)&outp[(size_t)(mlo+1)*NJ + 64 + tx*4] = make_float4(rhi[4],rhi[5],rhi[6],rhi[7]);
    }
}

// ---------------- split-K reduce + softmax (enemy) --------------------------
__global__ void k_redsm(const float* __restrict__ bias){
    __shared__ float red[128];
    int b = blockIdx.x, t = threadIdx.x;
    float s = bias[t];
    #pragma unroll 8
    for (int kz=0; kz<SPLITK; kz++) s += g_partial[(size_t)(kz*BB + b)*NJ + t];
    float v = s;
    red[t] = v; __syncthreads();
    for (int st=64; st; st>>=1){ if (t < st) red[t] = fmaxf(red[t], red[t+st]); __syncthreads(); }
    float mx = red[0]; __syncthreads();
    float e = expf(v - mx);
    red[t] = e; __syncthreads();
    for (int st=64; st; st>>=1){ if (t < st) red[t] += red[t+st]; __syncthreads(); }
    g_vec[b*128 + t] = e / red[0];
}

// ---------------- manipulator conv (collapsed) ------------------------------
__global__ void k_wsum(const float* __restrict__ mcw){
    int idx = blockIdx.x*256 + threadIdx.x;     // < 3*64*128
    if (idx >= 3*64*128) return;
    int v = idx / 8192;
    int rem = idx % 8192;           // o*128+c
    int base = rem*9 + 1;
    float w0 = mcw[base], w1 = mcw[base+3], w2 = mcw[base+6];
    g_Wsum[idx] = (v==0) ? (w1+w2) : (v==1) ? (w0+w1+w2) : (w0+w1);
}

__global__ void k_rgemm(const float* __restrict__ mcb){
    int idx = blockIdx.x*256 + threadIdx.x;     // < 3*BB*64
    if (idx >= 3*BB*64) return;
    int v = idx / (BB*64);
    int rem = idx % (BB*64);
    int b = rem / 64, o = rem % 64;
    const float* eo = g_vec + b*128;
    const float* ws = g_Wsum + v*8192 + o*128;
    float s = mcb[o];
    for (int c=0;c<128;c++) s = fmaf(eo[c], ws[c], s);
    g_r[idx] = fmaxf(s, 0.f);
}

__global__ void k_lmid(const float* __restrict__ mlw){
    int idx = blockIdx.x*256 + threadIdx.x;     // < 64*256
    if (idx >= 64*256) return;
    int o = idx >> 8, j = idx & 255;
    float s = 0.f;
    for (int h=1; h<127; h++) s += mlw[(size_t)(o*128 + h)*256 + j];
    g_Lmid[idx] = s;
}

__global__ void k_mtok(const float* __restrict__ mlw, const float* __restrict__ mlb){
    int idx = blockIdx.x*256 + threadIdx.x;     // < BB*256
    if (idx >= BB*256) return;
    int b = idx >> 8, j = idx & 255;
    const float* r0   = g_r + 0*BB*64 + b*64;
    const float* ri   = g_r + 1*BB*64 + b*64;
    const float* r127 = g_r + 2*BB*64 + b*64;
    float s = mlb[j];
    for (int o=0; o<64; o++){
        s = fmaf(r0[o],   mlw[(size_t)o*32768 + j],          s);
        s = fmaf(ri[o],   g_Lmid[o*256 + j],                 s);
        s = fmaf(r127[o], mlw[(size_t)o*32768 + 32512 + j],  s);
    }
    int t = (int)floorf(fabsf(s) * 100.0f);
    g_tok[idx] = t % VV;
}

// ---------------- friend: reduce + final linear + softmax -------------------
__global__ void k_redlin2(const float* __restrict__ bias, const float* __restrict__ w2,
                          const float* __restrict__ b2, float* __restrict__ out){
    __shared__ float f[128];
    int b = blockIdx.x, t = threadIdx.x;
    float s = bias[t];
    #pragma unroll 8
    for (int kz=0; kz<SPLITK; kz++) s += g_partial[(size_t)(kz*BB + b)*NJ + t];
    f[t] = s; __syncthreads();
    if (t < 32){
        float logit = -INFINITY;
        if (t < VV){
            logit = b2[t];
            for (int j=0; j<128; j++) logit = fmaf(f[j], w2[j*VV + t], logit);
        }
        float mx = logit;
        for (int off=16; off; off>>=1) mx = fmaxf(mx, __shfl_xor_sync(0xffffffffu, mx, off));
        float e = (t < VV) ? expf(logit - mx) : 0.f;
        float sm = e;
        for (int off=16; off; off>>=1) sm += __shfl_xor_sync(0xffffffffu, sm, off);
        if (t < VV) out[b*VV + t] = e / sm;
    }
}

// ---------------- launch ----------------------------------------------------
extern "C" void kernel_launch(void* const* d_in, const int* in_sizes, int n_in,
                              void* d_out, int out_size){
    const int*   x    = (const int*)  d_in[0];
    const float* eemb = (const float*)d_in[1];
    const float* ecw  = (const float*)d_in[2];
    const float* ecb  = (const float*)d_in[3];
    const float* elw  = (const float*)d_in[4];
    const float* elb  = (const float*)d_in[5];
    // d_in[6] rand_proj: dead (fog_of_war == identity permutation)
    const float* mcw  = (const float*)d_in[7];
    const float* mcb  = (const float*)d_in[8];
    const float* mlw  = (const float*)d_in[9];
    const float* mlb  = (const float*)d_in[10];
    const float* femb = (const float*)d_in[11];
    const float* fcw  = (const float*)d_in[12];
    const float* fcb  = (const float*)d_in[13];
    const float* flw1 = (const float*)d_in[14];
    const float* flb1 = (const float*)d_in[15];
    const float* flw2 = (const float*)d_in[16];
    const float* flb2 = (const float*)d_in[17];
    float* out = (float*)d_out;

    // LUT builds for both branches
    k_poolT2<<<(2*EMBD*NPP)/256, 256>>>(eemb, femb);
    k_pbuild2<<<dim3(32,4,2), 512>>>(ecw, fcw);
    k_pbreduce<<<(2*3*OC*NPP)/256, 256>>>();

    // enemy branch
    k_conv2<<<dim3(32,16), 256>>>(0, x, ecb);
    k_gemm2<<<dim3(2, SPLITK), 256>>>(elw);
    k_redsm<<<BB, 128>>>(elb);

    // manipulator -> tokens
    k_wsum<<<(3*64*128)/256, 256>>>(mcw);
    k_rgemm<<<(3*BB*64)/256, 256>>>(mcb);
    k_lmid<<<(64*256)/256, 256>>>(mlw);
    k_mtok<<<(BB*256)/256, 256>>>(mlw, mlb);

    // friend branch
    k_conv2<<<dim3(32,16), 256>>>(1, x, fcb);
    k_gemm2<<<dim3(2, SPLITK), 256>>>(flw1);
    k_redlin2<<<BB, 128>>>(flb1, flw2, flb2, out);
}

// round 6
// speedup vs baseline: 1.7160x; 1.1580x over previous
#include <cuda_runtime.h>
#include <math.h>

#define BB 256
#define LL 256
#define VV 14
#define EMBD 512
#define HH 128
#define OC 256
#define NP 196
#define NPP 256          // padded pair stride
#define KLIN 32768       // OC*HH
#define NJ 128
#define SPLITK 128
#define KC (KLIN/SPLITK) // 256 -> 2 output channels per split-K chunk

typedef unsigned long long ull;

// dynamic smem layout for k_gemmF
#define SM_AS    0                       // 2*16*128*4 = 16384
#define SM_BS    16384                   // 16384
#define SM_P2    32768                   // 6*256*4 = 6144
#define SM_SPI   38912                   // 128*132 = 16896
#define SM_BIAS  55808                   // 8
#define SM_TOTAL 55816

// ---------------- scratch ---------------------------------------------------
__device__ float g_poolT_e[EMBD*NPP];
__device__ float g_poolT_f[EMBD*NPP];
__device__ float g_pbpart[4*2*3*OC*NPP];   // [cs][br][kh][o][p]
__device__ float g_P2[2*3*OC*NPP];         // [br][kh][o][p]
__device__ unsigned char g_pi8T[2*HH*BB];  // [br][h][b] pair idx as uint8
__device__ float g_partial[SPLITK*BB*NJ];  // 16.8MB
__device__ float g_vec[BB*NJ];
__device__ float g_r[3*BB*64];
__device__ float g_Wsum[3*64*128];
__device__ float g_Lmid[64*256];
__device__ int   g_tok[BB*256];

// ---------------- f32x2 helpers --------------------------------------------
__device__ __forceinline__ ull pk2(float lo, float hi){
    ull r; asm("mov.b64 %0, {%1, %2};" : "=l"(r) : "f"(lo), "f"(hi)); return r;
}
__device__ __forceinline__ void upk2(ull v, float& lo, float& hi){
    asm("mov.b64 {%0, %1}, %2;" : "=f"(lo), "=f"(hi) : "l"(v));
}
__device__ __forceinline__ void ffma2(ull& c, ull a, ull b){
    asm("fma.rn.f32x2 %0, %1, %2, %0;" : "+l"(c) : "l"(a), "l"(b));
}

// ---------------- pooled-pair LUT, both branches ----------------------------
__global__ void k_poolT2(const float* __restrict__ eemb, const float* __restrict__ femb){
    int idx = blockIdx.x*256 + threadIdx.x;        // < 2*EMBD*NPP
    int br = idx / (EMBD*NPP);
    int r  = idx % (EMBD*NPP);
    int c = r >> 8, p = r & 255;
    const float* emb = br ? femb : eemb;
    float v = 0.f;
    if (p < NP){
        int t1 = p / VV, t2 = p % VV;
        v = fmaxf(emb[t1*EMBD + c], emb[t2*EMBD + c]);
    }
    (br ? g_poolT_f : g_poolT_e)[c*NPP + p] = v;
}

// ---------------- pbuild: P2 partials, c-split x4, both branches ------------
__global__ __launch_bounds__(512) void k_pbuild2(const float* __restrict__ ecw,
                                                 const float* __restrict__ fcw){
    int ot = blockIdx.x;          // 0..31 -> 8 o's
    int cs = blockIdx.y;          // 0..3  -> 128 c's
    int br = blockIdx.z;          // 0..1
    const float* cw    = br ? fcw : ecw;
    const float* poolT = br ? g_poolT_f : g_poolT_e;
    int o0 = ot*8, c0 = cs*128;
    __shared__ float ws[8*3*128];                 // [oi][kh][c]
    int tid = threadIdx.x;
    for (int e = tid; e < 3072; e += 512){
        int oi = e / 384, r = e % 384, kh = r >> 7, c = r & 127;
        ws[e] = cw[((size_t)(o0+oi)*EMBD + (c0+c))*9 + 1 + kh*3];
    }
    __syncthreads();
    int pg = tid & 63, oi = tid >> 6;
    int p0 = pg*4;
    ull acc0=0, acc1=0, acc2=0, acc3=0, acc4=0, acc5=0;   // [kh][pair]
    const float* pt  = poolT + (size_t)c0*NPP + p0;
    const float* wsp = ws + oi*384;
    #pragma unroll 4
    for (int c = 0; c < 128; c++){
        float4 pv = *(const float4*)(pt + (size_t)c*NPP);
        ull pa0 = pk2(pv.x, pv.y), pa1 = pk2(pv.z, pv.w);
        float w0 = wsp[c], w1 = wsp[128+c], w2 = wsp[256+c];
        ull b0 = pk2(w0,w0), b1 = pk2(w1,w1), b2 = pk2(w2,w2);
        ffma2(acc0, pa0, b0); ffma2(acc1, pa1, b0);
        ffma2(acc2, pa0, b1); ffma2(acc3, pa1, b1);
        ffma2(acc4, pa0, b2); ffma2(acc5, pa1, b2);
    }
    size_t base = (((size_t)(cs*2 + br)*3)*OC + (o0+oi))*NPP + p0;
    *(ulonglong2*)(g_pbpart + base)            = make_ulonglong2(acc0, acc1);
    *(ulonglong2*)(g_pbpart + base + OC*NPP)   = make_ulonglong2(acc2, acc3);
    *(ulonglong2*)(g_pbpart + base + 2*OC*NPP) = make_ulonglong2(acc4, acc5);
}

__global__ void k_pbreduce(){
    int idx = blockIdx.x*256 + threadIdx.x;        // < 2*3*OC*NPP
    int br = idx / (3*OC*NPP);
    int inner = idx % (3*OC*NPP);
    float s = g_pbpart[(0*2+br)*(3*OC*NPP) + inner]
            + g_pbpart[(1*2+br)*(3*OC*NPP) + inner]
            + g_pbpart[(2*2+br)*(3*OC*NPP) + inner]
            + g_pbpart[(3*2+br)*(3*OC*NPP) + inner];
    g_P2[idx] = s;
}

// ---------------- pair indices, transposed uint8: g_pi8T[br][h][b] ----------
__global__ void k_pairidx8(int which, const int* __restrict__ x){
    int idx = blockIdx.x*256 + threadIdx.x;        // < HH*BB, idx = h*BB + b
    int b = idx & 255, h = idx >> 8;
    const int* tok = which ? g_tok : x;
    g_pi8T[which*HH*BB + idx] =
        (unsigned char)(tok[b*LL + 2*h]*VV + tok[b*LL + 2*h + 1]);
}

// ---------------- fused conv+GEMM, split-K, f32x2, double-buffered ----------
// grid (2, SPLITK), block 256. Tile 128(M) x 128(N), K-chunk KC=256 (2 o's).
// A-tile values are computed on the fly from P2 LUT + pair indices in smem.
// Uses 55.8KB DYNAMIC shared memory (static cap is 48KB).
__global__ __launch_bounds__(256) void k_gemmF(int which, const float* __restrict__ W,
                                               const float* __restrict__ bias){
    extern __shared__ char dyn[];
    float (*As)[16][128]      = (float(*)[16][128])(dyn + SM_AS);
    float (*Bs)[16][128]      = (float(*)[16][128])(dyn + SM_BS);
    float (*sP2)[256]         = (float(*)[256])(dyn + SM_P2);
    unsigned char (*spi)[132] = (unsigned char(*)[132])(dyn + SM_SPI);
    float* sbias              = (float*)(dyn + SM_BIAS);

    int tid = threadIdx.x;
    int m0 = blockIdx.x * 128;
    int k0 = blockIdx.y * KC;
    int o0 = k0 >> 7;                      // this chunk's first output channel
    int lk = tid & 15, lm = tid >> 4;
    int bj = tid & 127, bk = tid >> 7;
    int tx = tid & 15, ty = tid >> 4;

    // stage LUTs (read-only for the whole block lifetime)
    const float* P2 = g_P2 + (size_t)which*(3*OC*NPP);
    for (int e = tid; e < 1536; e += 256){
        int kh = e / 512, r = e % 512, oi = r >> 8, p = r & 255;
        sP2[kh*2 + oi][p] = P2[(size_t)kh*OC*NPP + (o0+oi)*NPP + p];
    }
    const unsigned char* piT = g_pi8T + (size_t)which*(HH*BB);
    for (int e = tid; e < 4096; e += 256){          // uchar4 groups: h*32+g
        int h = e >> 5, g = e & 31;
        *(uchar4*)&spi[h][g*4] = *(const uchar4*)(piT + h*BB + m0 + g*4);
    }
    if (tid < 2) sbias[tid] = bias[o0 + tid];
    __syncthreads();

    ull acc[4][8];
    #pragma unroll
    for (int i=0;i<4;i++)
        #pragma unroll
        for (int j=0;j<8;j++) acc[i][j] = 0ull;

    float ra[8], rb[8];
    // ---- A-tile compute for k-slice starting at t (thread covers k=k0+t+lk)
    auto computeA = [&](int t, float* r){
        int k = k0 + t + lk;
        int h = k & 127;
        int oi = (k >> 7) - o0;            // 0 or 1
        const float* p2a = sP2[0 + oi];
        const float* p2b = sP2[2 + oi];
        const float* p2c = sP2[4 + oi];
        float vb = sbias[oi];
        bool hasA = (h > 0), hasC = (h < 127);
        #pragma unroll
        for (int i=0;i<8;i++){
            int m = lm + i*16;
            float v = vb;
            if (hasA) v += p2a[spi[h-1][m]];
            v += p2b[spi[h][m]];
            if (hasC) v += p2c[spi[h+1][m]];
            r[i] = v;
        }
    };

    // prologue: tile 0
    computeA(0, ra);
    #pragma unroll
    for (int i=0;i<8;i++) rb[i] = W[(size_t)(k0 + bk + i*2)*NJ + bj];
    #pragma unroll
    for (int i=0;i<8;i++) As[0][lk][lm + i*16] = ra[i];
    #pragma unroll
    for (int i=0;i<8;i++) Bs[0][bk + i*2][bj] = rb[i];
    __syncthreads();

    int buf = 0;
    for (int t = 16; t < KC; t += 16){
        computeA(t, ra);
        #pragma unroll
        for (int i=0;i<8;i++) rb[i] = W[(size_t)(k0 + t + bk + i*2)*NJ + bj];
        #pragma unroll
        for (int kk=0; kk<16; kk++){
            float4 a0 = *(const float4*)&As[buf][kk][ty*8];
            float4 a1 = *(const float4*)&As[buf][kk][ty*8 + 4];
            float4 b0 = *(const float4*)&Bs[buf][kk][tx*4];
            float4 b1 = *(const float4*)&Bs[buf][kk][64 + tx*4];
            ull ap[4] = { pk2(a0.x,a0.y), pk2(a0.z,a0.w),
                          pk2(a1.x,a1.y), pk2(a1.z,a1.w) };
            ull bd[8] = { pk2(b0.x,b0.x), pk2(b0.y,b0.y),
                          pk2(b0.z,b0.z), pk2(b0.w,b0.w),
                          pk2(b1.x,b1.x), pk2(b1.y,b1.y),
                          pk2(b1.z,b1.z), pk2(b1.w,b1.w) };
            #pragma unroll
            for (int i=0;i<4;i++)
                #pragma unroll
                for (int j=0;j<8;j++)
                    ffma2(acc[i][j], ap[i], bd[j]);
        }
        #pragma unroll
        for (int i=0;i<8;i++) As[buf^1][lk][lm + i*16] = ra[i];
        #pragma unroll
        for (int i=0;i<8;i++) Bs[buf^1][bk + i*2][bj] = rb[i];
        __syncthreads();
        buf ^= 1;
    }
    // final tile
    #pragma unroll
    for (int kk=0; kk<16; kk++){
        float4 a0 = *(const float4*)&As[buf][kk][ty*8];
        float4 a1 = *(const float4*)&As[buf][kk][ty*8 + 4];
        float4 b0 = *(const float4*)&Bs[buf][kk][tx*4];
        float4 b1 = *(const float4*)&Bs[buf][kk][64 + tx*4];
        ull ap[4] = { pk2(a0.x,a0.y), pk2(a0.z,a0.w),
                      pk2(a1.x,a1.y), pk2(a1.z,a1.w) };
        ull bd[8] = { pk2(b0.x,b0.x), pk2(b0.y,b0.y),
                      pk2(b0.z,b0.z), pk2(b0.w,b0.w),
                      pk2(b1.x,b1.x), pk2(b1.y,b1.y),
                      pk2(b1.z,b1.z), pk2(b1.w,b1.w) };
        #pragma unroll
        for (int i=0;i<4;i++)
            #pragma unroll
            for (int j=0;j<8;j++)
                ffma2(acc[i][j], ap[i], bd[j]);
    }

    float* outp = g_partial + (size_t)blockIdx.y * (BB*NJ);
    #pragma unroll
    for (int i=0;i<4;i++){
        int mlo = m0 + ty*8 + 2*i;
        float rlo[8], rhi[8];
        #pragma unroll
        for (int j=0;j<8;j++) upk2(acc[i][j], rlo[j], rhi[j]);
        *(float4*)&outp[(size_t)mlo*NJ + tx*4]          = make_float4(rlo[0],rlo[1],rlo[2],rlo[3]);
        *(float4*)&outp[(size_t)mlo*NJ + 64 + tx*4]     = make_float4(rlo[4],rlo[5],rlo[6],rlo[7]);
        *(float4*)&outp[(size_t)(mlo+1)*NJ + tx*4]      = make_float4(rhi[0],rhi[1],rhi[2],rhi[3]);
        *(float4*)&outp[(size_t)(mlo+1)*NJ + 64 + tx*4] = make_float4(rhi[4],rhi[5],rhi[6],rhi[7]);
    }
}

// ---------------- split-K reduce + softmax (enemy) --------------------------
__global__ void k_redsm(const float* __restrict__ bias){
    __shared__ float red[128];
    int b = blockIdx.x, t = threadIdx.x;
    float s = bias[t];
    #pragma unroll 8
    for (int kz=0; kz<SPLITK; kz++) s += g_partial[(size_t)(kz*BB + b)*NJ + t];
    float v = s;
    red[t] = v; __syncthreads();
    for (int st=64; st; st>>=1){ if (t < st) red[t] = fmaxf(red[t], red[t+st]); __syncthreads(); }
    float mx = red[0]; __syncthreads();
    float e = expf(v - mx);
    red[t] = e; __syncthreads();
    for (int st=64; st; st>>=1){ if (t < st) red[t] += red[t+st]; __syncthreads(); }
    g_vec[b*128 + t] = e / red[0];
}

// ---------------- manipulator conv (collapsed) ------------------------------
__global__ void k_wsum(const float* __restrict__ mcw){
    int idx = blockIdx.x*256 + threadIdx.x;     // < 3*64*128
    if (idx >= 3*64*128) return;
    int v = idx / 8192;
    int rem = idx % 8192;           // o*128+c
    int base = rem*9 + 1;
    float w0 = mcw[base], w1 = mcw[base+3], w2 = mcw[base+6];
    g_Wsum[idx] = (v==0) ? (w1+w2) : (v==1) ? (w0+w1+w2) : (w0+w1);
}

__global__ void k_rgemm(const float* __restrict__ mcb){
    int idx = blockIdx.x*256 + threadIdx.x;     // < 3*BB*64
    if (idx >= 3*BB*64) return;
    int v = idx / (BB*64);
    int rem = idx % (BB*64);
    int b = rem / 64, o = rem % 64;
    const float* eo = g_vec + b*128;
    const float* ws = g_Wsum + v*8192 + o*128;
    float s = mcb[o];
    for (int c=0;c<128;c++) s = fmaf(eo[c], ws[c], s);
    g_r[idx] = fmaxf(s, 0.f);
}

__global__ void k_lmid(const float* __restrict__ mlw){
    int idx = blockIdx.x*256 + threadIdx.x;     // < 64*256
    if (idx >= 64*256) return;
    int o = idx >> 8, j = idx & 255;
    float s = 0.f;
    for (int h=1; h<127; h++) s += mlw[(size_t)(o*128 + h)*256 + j];
    g_Lmid[idx] = s;
}

__global__ void k_mtok(const float* __restrict__ mlw, const float* __restrict__ mlb){
    int idx = blockIdx.x*256 + threadIdx.x;     // < BB*256
    if (idx >= BB*256) return;
    int b = idx >> 8, j = idx & 255;
    const float* r0   = g_r + 0*BB*64 + b*64;
    const float* ri   = g_r + 1*BB*64 + b*64;
    const float* r127 = g_r + 2*BB*64 + b*64;
    float s = mlb[j];
    for (int o=0; o<64; o++){
        s = fmaf(r0[o],   mlw[(size_t)o*32768 + j],          s);
        s = fmaf(ri[o],   g_Lmid[o*256 + j],                 s);
        s = fmaf(r127[o], mlw[(size_t)o*32768 + 32512 + j],  s);
    }
    int t = (int)floorf(fabsf(s) * 100.0f);
    g_tok[idx] = t % VV;
}

// ---------------- friend: reduce + final linear + softmax -------------------
__global__ void k_redlin2(const float* __restrict__ bias, const float* __restrict__ w2,
                          const float* __restrict__ b2, float* __restrict__ out){
    __shared__ float f[128];
    int b = blockIdx.x, t = threadIdx.x;
    float s = bias[t];
    #pragma unroll 8
    for (int kz=0; kz<SPLITK; kz++) s += g_partial[(size_t)(kz*BB + b)*NJ + t];
    f[t] = s; __syncthreads();
    if (t < 32){
        float logit = -INFINITY;
        if (t < VV){
            logit = b2[t];
            for (int j=0; j<128; j++) logit = fmaf(f[j], w2[j*VV + t], logit);
        }
        float mx = logit;
        for (int off=16; off; off>>=1) mx = fmaxf(mx, __shfl_xor_sync(0xffffffffu, mx, off));
        float e = (t < VV) ? expf(logit - mx) : 0.f;
        float sm = e;
        for (int off=16; off; off>>=1) sm += __shfl_xor_sync(0xffffffffu, sm, off);
        if (t < VV) out[b*VV + t] = e / sm;
    }
}

// ---------------- launch ----------------------------------------------------
extern "C" void kernel_launch(void* const* d_in, const int* in_sizes, int n_in,
                              void* d_out, int out_size){
    const int*   x    = (const int*)  d_in[0];
    const float* eemb = (const float*)d_in[1];
    const float* ecw  = (const float*)d_in[2];
    const float* ecb  = (const float*)d_in[3];
    const float* elw  = (const float*)d_in[4];
    const float* elb  = (const float*)d_in[5];
    // d_in[6] rand_proj: dead (fog_of_war == identity permutation)
    const float* mcw  = (const float*)d_in[7];
    const float* mcb  = (const float*)d_in[8];
    const float* mlw  = (const float*)d_in[9];
    const float* mlb  = (const float*)d_in[10];
    const float* femb = (const float*)d_in[11];
    const float* fcw  = (const float*)d_in[12];
    const float* fcb  = (const float*)d_in[13];
    const float* flw1 = (const float*)d_in[14];
    const float* flb1 = (const float*)d_in[15];
    const float* flw2 = (const float*)d_in[16];
    const float* flb2 = (const float*)d_in[17];
    float* out = (float*)d_out;

    // allow >48KB dynamic smem for the fused GEMM (host attr set, idempotent)
    cudaFuncSetAttribute(k_gemmF, cudaFuncAttributeMaxDynamicSharedMemorySize, SM_TOTAL);

    // LUT builds for both branches
    k_poolT2<<<(2*EMBD*NPP)/256, 256>>>(eemb, femb);
    k_pbuild2<<<dim3(32,4,2), 512>>>(ecw, fcw);
    k_pbreduce<<<(2*3*OC*NPP)/256, 256>>>();
    k_pairidx8<<<(HH*BB)/256, 256>>>(0, x);

    // enemy branch (conv fused into GEMM)
    k_gemmF<<<dim3(2, SPLITK), 256, SM_TOTAL>>>(0, elw, ecb);
    k_redsm<<<BB, 128>>>(elb);

    // manipulator -> tokens
    k_wsum<<<(3*64*128)/256, 256>>>(mcw);
    k_rgemm<<<(3*BB*64)/256, 256>>>(mcb);
    k_lmid<<<(64*256)/256, 256>>>(mlw);
    k_mtok<<<(BB*256)/256, 256>>>(mlw, mlb);
    k_pairidx8<<<(HH*BB)/256, 256>>>(1, x);

    // friend branch (conv fused into GEMM)
    k_gemmF<<<dim3(2, SPLITK), 256, SM_TOTAL>>>(1, flw1, fcb);
    k_redlin2<<<BB, 128>>>(flb1, flw2, flb2, out);
}